// round 16
// baseline (speedup 1.0000x reference)
#include <cuda_runtime.h>
#include <cuda_fp16.h>
#include <cstdint>
#include <cstring>

#define THREADS 768
#define TM 64

#define S0  56    // A0 / W0 stride (halves) = 112B
#define S2  136   // A2 / W1 stride (halves) = 272B

// ---- smem byte layout: shared weights + 3 per-group blocks ----
#define OFF_W0   0                       // 14336
#define OFF_W1   14336                   // 34816
#define GBASE    49152
#define GSTRIDE  25600                   // A0 7168 + A2 17408 + red 1024
#define OFF_B0S  (GBASE + 3*GSTRIDE)     // 125952
#define OFF_B1S  (OFF_B0S + 512)
#define OFF_W2S  (OFF_B1S + 512)
#define SMEM_BYTES (OFF_W2S + 512)       // 127488

__device__ __forceinline__ uint32_t s2u(const void* p){
    uint32_t a;
    asm("{ .reg .u64 t; cvta.to.shared.u64 t, %1; cvt.u32.u64 %0, t; }" : "=r"(a) : "l"(p));
    return a;
}
__device__ __forceinline__ void ldsm4(uint32_t r[4], uint32_t addr){
    asm volatile("ldmatrix.sync.aligned.m8n8.x4.shared.b16 {%0,%1,%2,%3}, [%4];"
                 : "=r"(r[0]), "=r"(r[1]), "=r"(r[2]), "=r"(r[3]) : "r"(addr));
}
__device__ __forceinline__ void stsm4(uint32_t addr, uint32_t r0, uint32_t r1,
                                      uint32_t r2, uint32_t r3){
    asm volatile("stmatrix.sync.aligned.m8n8.x4.shared.b16 [%0], {%1,%2,%3,%4};"
                 :: "r"(addr), "r"(r0), "r"(r1), "r"(r2), "r"(r3) : "memory");
}
__device__ __forceinline__ void mma_f16(float c[4], const uint32_t a[4],
                                        uint32_t b0, uint32_t b1){
    asm volatile("mma.sync.aligned.m16n8k16.row.col.f32.f16.f16.f32 "
                 "{%0,%1,%2,%3}, {%4,%5,%6,%7}, {%8,%9}, {%0,%1,%2,%3};"
                 : "+f"(c[0]), "+f"(c[1]), "+f"(c[2]), "+f"(c[3])
                 : "r"(a[0]), "r"(a[1]), "r"(a[2]), "r"(a[3]), "r"(b0), "r"(b1));
}
__device__ __forceinline__ float clip01(float v){ return fminf(fmaxf(v, 0.f), 1.f); }
__device__ __forceinline__ uint32_t pk2(float a, float b){
    __half2 h = __floats2half2_rn(a, b);
    uint32_t u; memcpy(&u, &h, 4); return u;
}
// per-group named barrier (ids 1..3), 256 threads each
#define GBAR(g) asm volatile("bar.sync %0, 256;" :: "r"((g) + 1) : "memory")

__global__ void __launch_bounds__(THREADS, 1)
mlp_occ_kernel(const float* __restrict__ x,
               const float* __restrict__ emb,
               const float* __restrict__ et,
               const float* __restrict__ W0,
               const float* __restrict__ b0,
               const float* __restrict__ W1,
               const float* __restrict__ b1,
               const float* __restrict__ W2,
               const float* __restrict__ b2,
               float* __restrict__ out,
               int Nq, int E, int ntiles)
{
    extern __shared__ __align__(1024) char smem[];
    const uint32_t sb = s2u(smem);
    const int tid = threadIdx.x;
    const int g   = tid >> 8;        // tile group 0/1/2
    const int t   = tid & 255;
    const int lane = t & 31, w = t >> 5;
    const int mw = w & 1, nw = w >> 1;     // 2 M-warps x 4 N-warps

    const int a0off = GBASE + g * GSTRIDE;
    const int a2off = a0off + 7168;
    const int rdoff = a2off + 17408;

    // ---- zero W0 pad + all A0 buffers; load biases ----
    for (int i = tid * 16; i < 14336; i += THREADS * 16)
        *(float4*)(smem + OFF_W0 + i) = make_float4(0.f, 0.f, 0.f, 0.f);
    for (int i = tid * 16; i < 3 * GSTRIDE; i += THREADS * 16){
        int gg = i / GSTRIDE, off = i % GSTRIDE;
        if (off < 7168)
            *(float4*)(smem + GBASE + gg * GSTRIDE + off) = make_float4(0.f, 0.f, 0.f, 0.f);
    }
    if (tid < 128){
        ((float*)(smem + OFF_B0S))[tid] = b0[tid];
        ((float*)(smem + OFF_B1S))[tid] = b1[tid];
        ((float*)(smem + OFF_W2S))[tid] = W2[tid];
    }
    __syncthreads();

    // ---- stage W0^T / W1^T fp16 (shared by all groups) ----
    for (int i = tid; i < 34 * 128; i += THREADS){
        int k = i >> 7, n = i & 127;
        *(__half*)(smem + OFF_W0 + (n * S0 + k) * 2) = __float2half_rn(W0[i]);
    }
    for (int i = tid; i < 128 * 128; i += THREADS){
        int k = i >> 7, n = i & 127;
        *(__half*)(smem + OFF_W1 + (n * S2 + k) * 2) = __float2half_rn(W1[i]);
    }
    __syncthreads();

    const float b2v = __ldg(b2);
    const float* b0s = (const float*)(smem + OFF_B0S);
    const float* b1s = (const float*)(smem + OFF_B1S);
    const float* w2s = (const float*)(smem + OFF_W2S);
    float* red = (float*)(smem + rdoff);

    // ---- ldmatrix / stmatrix lane bases ----
    const uint32_t aB0 = sb + a0off + ((mw * 32 + (lane & 15)) * S0) * 2 + (lane >> 4) * 16;
    const uint32_t aB1 = aB0 + 16 * S0 * 2;
    const uint32_t a2B0 = sb + a2off + ((mw * 32 + (lane & 15)) * S2) * 2 + (lane >> 4) * 16;
    const uint32_t a2B1 = a2B0 + 16 * S2 * 2;
    const int nrow = (lane & 7) + ((lane >> 4) << 3);
    const int bko  = ((lane >> 3) & 1) * 16;
    uint32_t w0B[2], w1B[2];
    #pragma unroll
    for (int q = 0; q < 2; q++){
        w0B[q] = sb + OFF_W0 + ((nw * 32 + q * 16 + nrow) * S0) * 2 + bko;
        w1B[q] = sb + OFF_W1 + ((nw * 32 + q * 16 + nrow) * S2) * 2 + bko;
    }
    const uint32_t stA2 = sb + a2off + ((mw * 32 + lane) * S2) * 2 + nw * 64;
    const int r0 = lane >> 2;
    const int cq = 2 * (lane & 3);

    // ---- prefetch first tile's emb/x (4 threads per point) ----
    const int m = t >> 2, q4 = t & 3;
    const int tstep = 3 * gridDim.x;
    float pf_ev = 0.f; float2 pf_x = make_float2(0.f, 0.f);
    {
        int t0 = blockIdx.x * 3 + g;
        int gm = t0 * TM + m;
        if (gm >= Nq) gm = Nq - 1;
        pf_ev = __ldg(emb + gm);
        if (q4 == 0) pf_x = *(const float2*)(x + 2 * gm);
    }

    for (int tile = blockIdx.x * 3 + g; tile < ntiles; tile += tstep){
        const int base = tile * TM;
        // no loop-top barrier (same hazard audit as R15)

        // ---- build A0 (fp16, cols 0..33; 34..47 stay zero) ----
        {
            float ev = pf_ev;
            int e1 = (int)ev;
            int e2 = e1 + 1; if (e2 > E - 1) e2 = E - 1;
            float res = ev - (float)e1;
            char* A0c = smem + a0off + m * S0 * 2;
            const float4* p1 = (const float4*)(et + e1 * 32 + q4 * 8);
            const float4* p2 = (const float4*)(et + e2 * 32 + q4 * 8);
            if (q4 == 0) *(uint32_t*)(A0c) = pk2(pf_x.x, pf_x.y);
            #pragma unroll
            for (int qq = 0; qq < 2; qq++){
                float4 u = p1[qq], v = p2[qq];
                float f0 = u.x + (v.x - u.x) * res;
                float f1 = u.y + (v.y - u.y) * res;
                float f2 = u.z + (v.z - u.z) * res;
                float f3 = u.w + (v.w - u.w) * res;
                int c = 2 + q4 * 8 + qq * 4;
                *(uint32_t*)(A0c + c * 2)       = pk2(f0, f1);
                *(uint32_t*)(A0c + (c + 2) * 2) = pk2(f2, f3);
            }
            int tile2 = tile + tstep;
            if (tile2 < ntiles){
                int gm2 = tile2 * TM + m; if (gm2 >= Nq) gm2 = Nq - 1;
                pf_ev = __ldg(emb + gm2);
                if (q4 == 0) pf_x = *(const float2*)(x + 2 * gm2);
            }
        }
        GBAR(g);

        // ---- layer 1: A0[64x48] x W0[48x32-chunk] (3 ksteps) ----
        float c[2][4][4];
        #pragma unroll
        for (int mi = 0; mi < 2; mi++)
            #pragma unroll
            for (int ni = 0; ni < 4; ni++)
                #pragma unroll
                for (int q = 0; q < 4; q++) c[mi][ni][q] = 0.f;
        #pragma unroll
        for (int ks = 0; ks < 3; ks++){
            uint32_t a0[4], a1[4], b[2][4];
            ldsm4(a0, aB0 + 32 * ks);
            ldsm4(a1, aB1 + 32 * ks);
            #pragma unroll
            for (int gg = 0; gg < 2; gg++) ldsm4(b[gg], w0B[gg] + 32 * ks);
            #pragma unroll
            for (int ni = 0; ni < 4; ni++){
                uint32_t b0v = b[ni >> 1][(ni & 1) * 2];
                uint32_t b1v = b[ni >> 1][(ni & 1) * 2 + 1];
                mma_f16(c[0][ni], a0, b0v, b1v);
                mma_f16(c[1][ni], a1, b0v, b1v);
            }
        }

        // ---- epilogue 1: +b0, clip, fp16 -> stmatrix + register A-frags ----
        uint32_t areg[2][2][4];
        #pragma unroll
        for (int ni = 0; ni < 4; ni++){
            int n = nw * 32 + ni * 8 + cq;
            float2 bb = *(const float2*)(b0s + n);
            uint32_t q0 = pk2(clip01(c[0][ni][0] + bb.x), clip01(c[0][ni][1] + bb.y));
            uint32_t q1 = pk2(clip01(c[0][ni][2] + bb.x), clip01(c[0][ni][3] + bb.y));
            uint32_t q2 = pk2(clip01(c[1][ni][0] + bb.x), clip01(c[1][ni][1] + bb.y));
            uint32_t q3 = pk2(clip01(c[1][ni][2] + bb.x), clip01(c[1][ni][3] + bb.y));
            stsm4(stA2 + ni * 16, q0, q1, q2, q3);
            const int j = ni >> 1, hh = (ni & 1) * 2;
            areg[j][0][hh]     = q0;
            areg[j][0][hh + 1] = q1;
            areg[j][1][hh]     = q2;
            areg[j][1][hh + 1] = q3;
        }

        // ---- layer 2 phase A (pre-barrier): own 2 ksteps from registers ----
        #pragma unroll
        for (int mi = 0; mi < 2; mi++)
            #pragma unroll
            for (int ni = 0; ni < 4; ni++)
                #pragma unroll
                for (int q = 0; q < 4; q++) c[mi][ni][q] = 0.f;
        #pragma unroll
        for (int j = 0; j < 2; j++){
            const int ks = nw * 2 + j;
            uint32_t b[2][4];
            #pragma unroll
            for (int gg = 0; gg < 2; gg++) ldsm4(b[gg], w1B[gg] + 32 * ks);
            #pragma unroll
            for (int ni = 0; ni < 4; ni++){
                uint32_t b0v = b[ni >> 1][(ni & 1) * 2];
                uint32_t b1v = b[ni >> 1][(ni & 1) * 2 + 1];
                mma_f16(c[0][ni], areg[j][0], b0v, b1v);
                mma_f16(c[1][ni], areg[j][1], b0v, b1v);
            }
        }
        GBAR(g);   // partner warps' stmatrix now visible

        // ---- layer 2 phase B: 6 partner ksteps from smem ----
        #pragma unroll
        for (int p = 1; p < 4; p++){
            const int nwp = (nw + p) & 3;
            #pragma unroll
            for (int j = 0; j < 2; j++){
                const int ks = nwp * 2 + j;
                uint32_t a0[4], a1[4], b[2][4];
                ldsm4(a0, a2B0 + 32 * ks);
                ldsm4(a1, a2B1 + 32 * ks);
                #pragma unroll
                for (int gg = 0; gg < 2; gg++) ldsm4(b[gg], w1B[gg] + 32 * ks);
                #pragma unroll
                for (int ni = 0; ni < 4; ni++){
                    uint32_t b0v = b[ni >> 1][(ni & 1) * 2];
                    uint32_t b1v = b[ni >> 1][(ni & 1) * 2 + 1];
                    mma_f16(c[0][ni], a0, b0v, b1v);
                    mma_f16(c[1][ni], a1, b0v, b1v);
                }
            }
        }

        // ---- epilogue 2: +b1, clip, dot W2, reduce, sigmoid ----
        {
            float acc[2][2] = {{0.f, 0.f}, {0.f, 0.f}};
            #pragma unroll
            for (int mi = 0; mi < 2; mi++)
                #pragma unroll
                for (int ni = 0; ni < 4; ni++){
                    int n = nw * 32 + ni * 8 + cq;
                    float2 bb = *(const float2*)(b1s + n);
                    float2 ww = *(const float2*)(w2s + n);
                    acc[mi][0] = fmaf(clip01(c[mi][ni][0] + bb.x), ww.x,
                                 fmaf(clip01(c[mi][ni][1] + bb.y), ww.y, acc[mi][0]));
                    acc[mi][1] = fmaf(clip01(c[mi][ni][2] + bb.x), ww.x,
                                 fmaf(clip01(c[mi][ni][3] + bb.y), ww.y, acc[mi][1]));
                }
            #pragma unroll
            for (int mi = 0; mi < 2; mi++)
                #pragma unroll
                for (int hb = 0; hb < 2; hb++){
                    float v = acc[mi][hb];
                    v += __shfl_xor_sync(0xffffffffu, v, 1);
                    v += __shfl_xor_sync(0xffffffffu, v, 2);
                    if ((lane & 3) == 0)
                        red[(mw * 32 + mi * 16 + r0 + hb * 8) * 4 + nw] = v;
                }
        }
        GBAR(g);

        if (t < TM){
            const float4 r4 = *(const float4*)(red + t * 4);
            float z = b2v + r4.x + r4.y + r4.z + r4.w;
            float o = 1.f / (1.f + __expf(-z));
            int gm = base + t;
            if (gm < Nq) out[gm] = o;
        }
    }
}

extern "C" void kernel_launch(void* const* d_in, const int* in_sizes, int n_in,
                              void* d_out, int out_size)
{
    const float* x   = (const float*)d_in[0];
    const float* emb = (const float*)d_in[1];
    const float* et  = (const float*)d_in[2];
    const float* W0  = (const float*)d_in[3];
    const float* b0  = (const float*)d_in[4];
    const float* W1  = (const float*)d_in[5];
    const float* b1  = (const float*)d_in[6];
    const float* W2  = (const float*)d_in[7];
    const float* b2  = (const float*)d_in[8];
    float* out = (float*)d_out;

    const int Nq = in_sizes[1];
    const int E  = in_sizes[2] / 32;
    const int ntiles = (Nq + TM - 1) / TM;

    cudaFuncSetAttribute(mlp_occ_kernel,
                         cudaFuncAttributeMaxDynamicSharedMemorySize, SMEM_BYTES);
    int sms = 148;
    cudaDeviceGetAttribute(&sms, cudaDevAttrMultiProcessorCount, 0);
    int grid = (ntiles + 2) / 3;
    if (grid > sms) grid = sms;

    mlp_occ_kernel<<<grid, THREADS, SMEM_BYTES>>>(
        x, emb, et, W0, b0, W1, b1, W2, b2, out, Nq, E, ntiles);
}

// round 17
// speedup vs baseline: 1.0146x; 1.0146x over previous
#include <cuda_runtime.h>
#include <cuda_fp16.h>
#include <cstdint>
#include <cstring>

#define THREADS 768
#define TM 64

#define S0  56    // A0 / W0 stride (halves) = 112B
#define S2  136   // A2 / W1 stride (halves) = 272B

// ---- smem byte layout: shared weights + 3 per-group blocks ----
#define OFF_W0   0                       // 14336
#define OFF_W1   14336                   // 34816
#define GBASE    49152
#define GSTRIDE  25600                   // A0 7168 + A2 17408 + red 1024
#define OFF_B0S  (GBASE + 3*GSTRIDE)     // 125952
#define OFF_B1S  (OFF_B0S + 512)
#define OFF_W2S  (OFF_B1S + 512)
#define SMEM_BYTES (OFF_W2S + 512)       // 127488

__device__ __forceinline__ uint32_t s2u(const void* p){
    uint32_t a;
    asm("{ .reg .u64 t; cvta.to.shared.u64 t, %1; cvt.u32.u64 %0, t; }" : "=r"(a) : "l"(p));
    return a;
}
__device__ __forceinline__ void ldsm4(uint32_t r[4], uint32_t addr){
    asm volatile("ldmatrix.sync.aligned.m8n8.x4.shared.b16 {%0,%1,%2,%3}, [%4];"
                 : "=r"(r[0]), "=r"(r[1]), "=r"(r[2]), "=r"(r[3]) : "r"(addr));
}
__device__ __forceinline__ void stsm4(uint32_t addr, uint32_t r0, uint32_t r1,
                                      uint32_t r2, uint32_t r3){
    asm volatile("stmatrix.sync.aligned.m8n8.x4.shared.b16 [%0], {%1,%2,%3,%4};"
                 :: "r"(addr), "r"(r0), "r"(r1), "r"(r2), "r"(r3) : "memory");
}
__device__ __forceinline__ void mma_f16(float c[4], const uint32_t a[4],
                                        uint32_t b0, uint32_t b1){
    asm volatile("mma.sync.aligned.m16n8k16.row.col.f32.f16.f16.f32 "
                 "{%0,%1,%2,%3}, {%4,%5,%6,%7}, {%8,%9}, {%0,%1,%2,%3};"
                 : "+f"(c[0]), "+f"(c[1]), "+f"(c[2]), "+f"(c[3])
                 : "r"(a[0]), "r"(a[1]), "r"(a[2]), "r"(a[3]), "r"(b0), "r"(b1));
}
__device__ __forceinline__ float clip01(float v){ return fminf(fmaxf(v, 0.f), 1.f); }
__device__ __forceinline__ uint32_t pk2(float a, float b){
    __half2 h = __floats2half2_rn(a, b);
    uint32_t u; memcpy(&u, &h, 4); return u;
}
// per-group named barrier (ids 1..3), 256 threads each
#define GBAR(g) asm volatile("bar.sync %0, 256;" :: "r"((g) + 1) : "memory")

__global__ void __launch_bounds__(THREADS, 1)
mlp_occ2_kernel(const float* __restrict__ x,
                const float* __restrict__ emb,
                const float* __restrict__ et,
                const float* __restrict__ W0,
                const float* __restrict__ b0,
                const float* __restrict__ W1,
                const float* __restrict__ b1,
                const float* __restrict__ W2,
                const float* __restrict__ b2,
                float* __restrict__ out,
                int Nq, int E, int ntiles)
{
    extern __shared__ __align__(1024) char smem[];
    const uint32_t sb = s2u(smem);
    const int tid = threadIdx.x;
    const int g   = tid >> 8;        // tile group 0/1/2
    const int t   = tid & 255;
    const int lane = t & 31, w = t >> 5;
    const int mw = w & 1, nw = w >> 1;     // 2 M-warps x 4 N-warps

    const int a0off = GBASE + g * GSTRIDE;
    const int a2off = a0off + 7168;
    const int rdoff = a2off + 17408;

    // ---- zero W0 pad + all A0 buffers; load biases ----
    for (int i = tid * 16; i < 14336; i += THREADS * 16)
        *(float4*)(smem + OFF_W0 + i) = make_float4(0.f, 0.f, 0.f, 0.f);
    for (int i = tid * 16; i < 3 * GSTRIDE; i += THREADS * 16){
        int gg = i / GSTRIDE, off = i % GSTRIDE;
        if (off < 7168)
            *(float4*)(smem + GBASE + gg * GSTRIDE + off) = make_float4(0.f, 0.f, 0.f, 0.f);
    }
    if (tid < 128){
        ((float*)(smem + OFF_B0S))[tid] = b0[tid];
        ((float*)(smem + OFF_B1S))[tid] = b1[tid];
        ((float*)(smem + OFF_W2S))[tid] = W2[tid];
    }
    __syncthreads();

    // ---- stage W0^T / W1^T fp16 (shared by all groups) ----
    for (int i = tid; i < 34 * 128; i += THREADS){
        int k = i >> 7, n = i & 127;
        *(__half*)(smem + OFF_W0 + (n * S0 + k) * 2) = __float2half_rn(W0[i]);
    }
    for (int i = tid; i < 128 * 128; i += THREADS){
        int k = i >> 7, n = i & 127;
        *(__half*)(smem + OFF_W1 + (n * S2 + k) * 2) = __float2half_rn(W1[i]);
    }
    __syncthreads();

    const float b2v = __ldg(b2);
    const float* b0s = (const float*)(smem + OFF_B0S);
    const float* b1s = (const float*)(smem + OFF_B1S);
    const float* w2s = (const float*)(smem + OFF_W2S);
    float* red = (float*)(smem + rdoff);

    // ---- ldmatrix / stmatrix lane bases ----
    const uint32_t aB0 = sb + a0off + ((mw * 32 + (lane & 15)) * S0) * 2 + (lane >> 4) * 16;
    const uint32_t aB1 = aB0 + 16 * S0 * 2;
    const uint32_t a2B0 = sb + a2off + ((mw * 32 + (lane & 15)) * S2) * 2 + (lane >> 4) * 16;
    const uint32_t a2B1 = a2B0 + 16 * S2 * 2;
    const int nrow = (lane & 7) + ((lane >> 4) << 3);
    const int bko  = ((lane >> 3) & 1) * 16;
    uint32_t w0B[2], w1B[2];
    #pragma unroll
    for (int q = 0; q < 2; q++){
        w0B[q] = sb + OFF_W0 + ((nw * 32 + q * 16 + nrow) * S0) * 2 + bko;
        w1B[q] = sb + OFF_W1 + ((nw * 32 + q * 16 + nrow) * S2) * 2 + bko;
    }
    const uint32_t stA2 = sb + a2off + ((mw * 32 + lane) * S2) * 2 + nw * 64;
    const int r0 = lane >> 2;
    const int cq = 2 * (lane & 3);

    // ---- prefetch first tile's emb/x (4 threads per point; lane 4*pl holds ev) ----
    const int m = t >> 2, q4 = t & 3;
    const int tstep = 3 * gridDim.x;
    float pf_ev = 0.f; float2 pf_x = make_float2(0.f, 0.f);
    {
        int t0 = blockIdx.x * 3 + g;
        int gm = t0 * TM + m;
        if (gm >= Nq) gm = Nq - 1;
        pf_ev = __ldg(emb + gm);
        if (q4 == 0) pf_x = *(const float2*)(x + 2 * gm);
    }

    const float4* et4 = (const float4*)et;

    for (int tile = blockIdx.x * 3 + g; tile < ntiles; tile += tstep){
        const int base = tile * TM;
        // no loop-top barrier (same hazard audit as R15)

        // ---- build A0: coalesced gather (lane l -> chunk q=l&7 of point 4j+(l>>3)) ----
        {
            #pragma unroll
            for (int j = 0; j < 2; j++){
                int pl = 4 * j + (lane >> 3);          // local point 0..7 in this warp
                float ev = __shfl_sync(0xffffffffu, pf_ev, 4 * pl);
                int e1 = (int)ev;
                int e2 = e1 + 1; if (e2 > E - 1) e2 = E - 1;
                float res = ev - (float)e1;
                int q = lane & 7;                      // 16B chunk within 128B row
                float4 u = __ldg(et4 + e1 * 8 + q);    // lanes 0-7 same row: coalesced
                float4 v = __ldg(et4 + e2 * 8 + q);
                int mm = w * 8 + pl;
                char* dst = smem + a0off + (mm * S0 + 2 + 4 * q) * 2;
                *(uint32_t*)(dst)     = pk2(u.x + (v.x - u.x) * res, u.y + (v.y - u.y) * res);
                *(uint32_t*)(dst + 4) = pk2(u.z + (v.z - u.z) * res, u.w + (v.w - u.w) * res);
            }
            if (q4 == 0)
                *(uint32_t*)(smem + a0off + m * S0 * 2) = pk2(pf_x.x, pf_x.y);
            // prefetch next tile's emb/x (after shfl consumers above)
            int tile2 = tile + tstep;
            if (tile2 < ntiles){
                int gm2 = tile2 * TM + m; if (gm2 >= Nq) gm2 = Nq - 1;
                pf_ev = __ldg(emb + gm2);
                if (q4 == 0) pf_x = *(const float2*)(x + 2 * gm2);
            }
        }
        GBAR(g);

        // ---- layer 1: A0[64x48] x W0[48x32-chunk] (3 ksteps) ----
        float c[2][4][4];
        #pragma unroll
        for (int mi = 0; mi < 2; mi++)
            #pragma unroll
            for (int ni = 0; ni < 4; ni++)
                #pragma unroll
                for (int q = 0; q < 4; q++) c[mi][ni][q] = 0.f;
        #pragma unroll
        for (int ks = 0; ks < 3; ks++){
            uint32_t a0[4], a1[4], b[2][4];
            ldsm4(a0, aB0 + 32 * ks);
            ldsm4(a1, aB1 + 32 * ks);
            #pragma unroll
            for (int gg = 0; gg < 2; gg++) ldsm4(b[gg], w0B[gg] + 32 * ks);
            #pragma unroll
            for (int ni = 0; ni < 4; ni++){
                uint32_t b0v = b[ni >> 1][(ni & 1) * 2];
                uint32_t b1v = b[ni >> 1][(ni & 1) * 2 + 1];
                mma_f16(c[0][ni], a0, b0v, b1v);
                mma_f16(c[1][ni], a1, b0v, b1v);
            }
        }

        // ---- epilogue 1: +b0, clip, fp16 -> stmatrix + register A-frags ----
        uint32_t areg[2][2][4];
        #pragma unroll
        for (int ni = 0; ni < 4; ni++){
            int n = nw * 32 + ni * 8 + cq;
            float2 bb = *(const float2*)(b0s + n);
            uint32_t q0 = pk2(clip01(c[0][ni][0] + bb.x), clip01(c[0][ni][1] + bb.y));
            uint32_t q1 = pk2(clip01(c[0][ni][2] + bb.x), clip01(c[0][ni][3] + bb.y));
            uint32_t q2 = pk2(clip01(c[1][ni][0] + bb.x), clip01(c[1][ni][1] + bb.y));
            uint32_t q3 = pk2(clip01(c[1][ni][2] + bb.x), clip01(c[1][ni][3] + bb.y));
            stsm4(stA2 + ni * 16, q0, q1, q2, q3);
            const int j = ni >> 1, hh = (ni & 1) * 2;
            areg[j][0][hh]     = q0;
            areg[j][0][hh + 1] = q1;
            areg[j][1][hh]     = q2;
            areg[j][1][hh + 1] = q3;
        }

        // ---- layer 2 phase A (pre-barrier): own 2 ksteps from registers ----
        #pragma unroll
        for (int mi = 0; mi < 2; mi++)
            #pragma unroll
            for (int ni = 0; ni < 4; ni++)
                #pragma unroll
                for (int q = 0; q < 4; q++) c[mi][ni][q] = 0.f;
        #pragma unroll
        for (int j = 0; j < 2; j++){
            const int ks = nw * 2 + j;
            uint32_t b[2][4];
            #pragma unroll
            for (int gg = 0; gg < 2; gg++) ldsm4(b[gg], w1B[gg] + 32 * ks);
            #pragma unroll
            for (int ni = 0; ni < 4; ni++){
                uint32_t b0v = b[ni >> 1][(ni & 1) * 2];
                uint32_t b1v = b[ni >> 1][(ni & 1) * 2 + 1];
                mma_f16(c[0][ni], areg[j][0], b0v, b1v);
                mma_f16(c[1][ni], areg[j][1], b0v, b1v);
            }
        }
        GBAR(g);   // partner warps' stmatrix now visible

        // ---- layer 2 phase B: 6 partner ksteps from smem ----
        #pragma unroll
        for (int p = 1; p < 4; p++){
            const int nwp = (nw + p) & 3;
            #pragma unroll
            for (int j = 0; j < 2; j++){
                const int ks = nwp * 2 + j;
                uint32_t a0[4], a1[4], b[2][4];
                ldsm4(a0, a2B0 + 32 * ks);
                ldsm4(a1, a2B1 + 32 * ks);
                #pragma unroll
                for (int gg = 0; gg < 2; gg++) ldsm4(b[gg], w1B[gg] + 32 * ks);
                #pragma unroll
                for (int ni = 0; ni < 4; ni++){
                    uint32_t b0v = b[ni >> 1][(ni & 1) * 2];
                    uint32_t b1v = b[ni >> 1][(ni & 1) * 2 + 1];
                    mma_f16(c[0][ni], a0, b0v, b1v);
                    mma_f16(c[1][ni], a1, b0v, b1v);
                }
            }
        }

        // ---- epilogue 2: +b1, clip, dot W2, reduce, sigmoid ----
        {
            float acc[2][2] = {{0.f, 0.f}, {0.f, 0.f}};
            #pragma unroll
            for (int mi = 0; mi < 2; mi++)
                #pragma unroll
                for (int ni = 0; ni < 4; ni++){
                    int n = nw * 32 + ni * 8 + cq;
                    float2 bb = *(const float2*)(b1s + n);
                    float2 ww = *(const float2*)(w2s + n);
                    acc[mi][0] = fmaf(clip01(c[mi][ni][0] + bb.x), ww.x,
                                 fmaf(clip01(c[mi][ni][1] + bb.y), ww.y, acc[mi][0]));
                    acc[mi][1] = fmaf(clip01(c[mi][ni][2] + bb.x), ww.x,
                                 fmaf(clip01(c[mi][ni][3] + bb.y), ww.y, acc[mi][1]));
                }
            #pragma unroll
            for (int mi = 0; mi < 2; mi++)
                #pragma unroll
                for (int hb = 0; hb < 2; hb++){
                    float v = acc[mi][hb];
                    v += __shfl_xor_sync(0xffffffffu, v, 1);
                    v += __shfl_xor_sync(0xffffffffu, v, 2);
                    if ((lane & 3) == 0)
                        red[(mw * 32 + mi * 16 + r0 + hb * 8) * 4 + nw] = v;
                }
        }
        GBAR(g);

        if (t < TM){
            const float4 r4 = *(const float4*)(red + t * 4);
            float z = b2v + r4.x + r4.y + r4.z + r4.w;
            float o = 1.f / (1.f + __expf(-z));
            int gm = base + t;
            if (gm < Nq) out[gm] = o;
        }
    }
}

extern "C" void kernel_launch(void* const* d_in, const int* in_sizes, int n_in,
                              void* d_out, int out_size)
{
    const float* x   = (const float*)d_in[0];
    const float* emb = (const float*)d_in[1];
    const float* et  = (const float*)d_in[2];
    const float* W0  = (const float*)d_in[3];
    const float* b0  = (const float*)d_in[4];
    const float* W1  = (const float*)d_in[5];
    const float* b1  = (const float*)d_in[6];
    const float* W2  = (const float*)d_in[7];
    const float* b2  = (const float*)d_in[8];
    float* out = (float*)d_out;

    const int Nq = in_sizes[1];
    const int E  = in_sizes[2] / 32;
    const int ntiles = (Nq + TM - 1) / TM;

    cudaFuncSetAttribute(mlp_occ2_kernel,
                         cudaFuncAttributeMaxDynamicSharedMemorySize, SMEM_BYTES);
    int sms = 148;
    cudaDeviceGetAttribute(&sms, cudaDevAttrMultiProcessorCount, 0);
    int grid = (ntiles + 2) / 3;
    if (grid > sms) grid = sms;

    mlp_occ2_kernel<<<grid, THREADS, SMEM_BYTES>>>(
        x, emb, et, W0, b0, W1, b1, W2, b2, out, Nq, E, ntiles);
}